// round 1
// baseline (speedup 1.0000x reference)
#include <cuda_runtime.h>
#include <cuda_bf16.h>
#include <cstdint>

// ---------------------------------------------------------------------------
// RnnTfModel: emb lookup -> LSTM1 (seq) -> LSTM2 (last) -> heads
// B=512, T=1024, D=H=64, 4H=256, V=8193
//
// Plan:
//   k_embproj : g_table[v][j] = sum_k emb[v][k]*W1[k][j] + b1[j]   (8193x256)
//   k_lstm    : persistent fused 2-layer LSTM. 128 blocks x 4 rows, 256 thr.
//               weights in smem, packed f32x2 FMA, h broadcast via smem,
//               c in registers. Writes final h2 -> g_h2.
//   k_head    : BN + MLP + softmax head and langmodel sigmoid head.
// ---------------------------------------------------------------------------

#define B_   512
#define T_   1024
#define D_   64
#define G4_  256
#define V_   8193
#define NB_  4
#define NBLK_ 128
#define THR_ 256

using ull = unsigned long long;

__device__ float g_table[V_ * G4_];   // projected embedding table (8.4 MB)
__device__ float g_h2[B_ * D_];       // final layer-2 hidden state

__device__ __forceinline__ void ffma2(ull& d, ull a, ull b) {
    asm("fma.rn.f32x2 %0, %1, %2, %0;" : "+l"(d) : "l"(a), "l"(b));
}
__device__ __forceinline__ float2 unpack2(ull v) {
    float2 f;
    asm("mov.b64 {%0, %1}, %2;" : "=f"(f.x), "=f"(f.y) : "l"(v));
    return f;
}
__device__ __forceinline__ float sigm_(float x) {
    return 1.0f / (1.0f + __expf(-x));
}
__device__ __forceinline__ float tanh_(float x) {
    float e = __expf(-2.0f * x);
    return (1.0f - e) / (1.0f + e);
}

// ---------------------------------------------------------------------------
// Kernel 1: projected embedding table  (g_table = emb @ W1 + b1)
// ---------------------------------------------------------------------------
__global__ void k_embproj(const float* __restrict__ emb,
                          const float* __restrict__ W1,
                          const float* __restrict__ b1) {
    int v = blockIdx.x;
    int j = threadIdx.x;  // 256 threads, one output each
    __shared__ float e[D_];
    if (j < D_) e[j] = emb[v * D_ + j];
    __syncthreads();
    float acc = b1[j];
#pragma unroll
    for (int k = 0; k < D_; k++) acc += e[k] * __ldg(&W1[k * G4_ + j]);
    g_table[v * G4_ + j] = acc;
}

// ---------------------------------------------------------------------------
// Kernel 2: fused persistent 2-layer LSTM
// Dynamic smem layout (floats):
//   [0,      16384)  U1q   : U1 k-interleaved float4: (k4*256+j)*4+kk = U1[4k4+kk][j]
//   [16384,  49152)  WU2q  : rows 0..63 = W2, 64..127 = U2, same interleave
//   [49152,  49664)  hc    : 4 rows x 128 : [0,64)=h1, [64,128)=h2
//   [49664,  50688)  zbuf  : 4 rows x 256 gate activations
//   [50688,  54784)  code_s: 4 rows x 1024 int32
// total = 219136 bytes
// ---------------------------------------------------------------------------
#define SMEM_FLOATS 50688
#define SMEM_BYTES  (SMEM_FLOATS * 4 + NB_ * T_ * 4)

__global__ void __launch_bounds__(THR_, 1)
k_lstm(const int* __restrict__ code_in,
       const float* __restrict__ U1,
       const float* __restrict__ W2,
       const float* __restrict__ U2,
       const float* __restrict__ b2) {
    extern __shared__ float smem[];
    float* U1q   = smem;                      // 16384
    float* WU2q  = smem + 16384;              // 32768
    float* hc    = smem + 49152;              // 512
    float* zbuf  = smem + 49664;              // 1024
    int*   code_s = (int*)(smem + 50688);     // 4096 ints

    const int j  = threadIdx.x;
    const int r_ = j >> 6;      // row for c/h update role
    const int u_ = j & 63;      // hidden unit for c/h update role
    const int b0 = blockIdx.x * NB_;

    // ---- load weights into smem (k-interleaved-by-4 layout) ----
    for (int i = j; i < D_ * G4_; i += THR_) {
        int k = i >> 8, jj = i & 255;
        int k4 = k >> 2, kk = k & 3;
        U1q[(k4 * G4_ + jj) * 4 + kk] = U1[i];
    }
    for (int i = j; i < 2 * D_ * G4_; i += THR_) {
        int k = i >> 8, jj = i & 255;
        int k4 = k >> 2, kk = k & 3;
        float w = (k < D_) ? W2[k * G4_ + jj] : U2[(k - D_) * G4_ + jj];
        WU2q[(k4 * G4_ + jj) * 4 + kk] = w;
    }
    // ---- load codes for this block's 4 rows ----
    for (int i = j; i < NB_ * T_; i += THR_) {
        int r = i >> 10, t = i & (T_ - 1);
        code_s[i] = code_in[(b0 + r) * T_ + t];
    }
    // ---- zero h state ----
    hc[j] = 0.0f;
    hc[j + 256] = 0.0f;
    __syncthreads();

    const float b2j = b2[j];
    float c1 = 0.0f, c2 = 0.0f;

    // prefetch xz for t=0
    float cur[NB_];
#pragma unroll
    for (int r = 0; r < NB_; r++)
        cur[r] = __ldg(&g_table[(size_t)code_s[r * T_] * G4_ + j]);

    const bool isg = ((j >> 6) == 2);  // gate index 2 = g (tanh)

    for (int t = 0; t < T_; t++) {
        // prefetch next timestep's input projection (latency hidden by matvecs)
        float nxt[NB_];
        int tn = (t + 1 < T_) ? (t + 1) : (T_ - 1);
#pragma unroll
        for (int r = 0; r < NB_; r++)
            nxt[r] = __ldg(&g_table[(size_t)code_s[r * T_ + tn] * G4_ + j]);

        // ---------------- layer 1 matvec: z1 = xz + h1 @ U1 ----------------
        ull a0 = 0, a1 = 0, a2 = 0, a3 = 0;
#pragma unroll
        for (int k4 = 0; k4 < 16; k4++) {
            ulonglong2 uq = *(const ulonglong2*)&U1q[(k4 * G4_ + j) * 4];
            ulonglong2 h0 = *(const ulonglong2*)&hc[0 * 128 + 4 * k4];
            ulonglong2 h1 = *(const ulonglong2*)&hc[1 * 128 + 4 * k4];
            ulonglong2 h2 = *(const ulonglong2*)&hc[2 * 128 + 4 * k4];
            ulonglong2 h3 = *(const ulonglong2*)&hc[3 * 128 + 4 * k4];
            ffma2(a0, h0.x, uq.x); ffma2(a1, h1.x, uq.x);
            ffma2(a2, h2.x, uq.x); ffma2(a3, h3.x, uq.x);
            ffma2(a0, h0.y, uq.y); ffma2(a1, h1.y, uq.y);
            ffma2(a2, h2.y, uq.y); ffma2(a3, h3.y, uq.y);
        }
        {
            ull aa[NB_] = {a0, a1, a2, a3};
#pragma unroll
            for (int r = 0; r < NB_; r++) {
                float2 p = unpack2(aa[r]);
                float z = cur[r] + p.x + p.y;
                zbuf[r * G4_ + j] = isg ? tanh_(z) : sigm_(z);
            }
        }
        __syncthreads();
        {
            float iv = zbuf[r_ * G4_ + u_];
            float fv = zbuf[r_ * G4_ + 64 + u_];
            float gv = zbuf[r_ * G4_ + 128 + u_];
            float ov = zbuf[r_ * G4_ + 192 + u_];
            c1 = fv * c1 + iv * gv;
            hc[r_ * 128 + u_] = ov * tanh_(c1);   // h1_t
        }
        __syncthreads();

        // -------- layer 2 matvec: z2 = b2 + [h1_t, h2_{t-1}] @ [W2;U2] -----
        a0 = a1 = a2 = a3 = 0;
#pragma unroll
        for (int k4 = 0; k4 < 32; k4++) {
            ulonglong2 uq = *(const ulonglong2*)&WU2q[(k4 * G4_ + j) * 4];
            ulonglong2 h0 = *(const ulonglong2*)&hc[0 * 128 + 4 * k4];
            ulonglong2 h1 = *(const ulonglong2*)&hc[1 * 128 + 4 * k4];
            ulonglong2 h2 = *(const ulonglong2*)&hc[2 * 128 + 4 * k4];
            ulonglong2 h3 = *(const ulonglong2*)&hc[3 * 128 + 4 * k4];
            ffma2(a0, h0.x, uq.x); ffma2(a1, h1.x, uq.x);
            ffma2(a2, h2.x, uq.x); ffma2(a3, h3.x, uq.x);
            ffma2(a0, h0.y, uq.y); ffma2(a1, h1.y, uq.y);
            ffma2(a2, h2.y, uq.y); ffma2(a3, h3.y, uq.y);
        }
        {
            ull aa[NB_] = {a0, a1, a2, a3};
#pragma unroll
            for (int r = 0; r < NB_; r++) {
                float2 p = unpack2(aa[r]);
                float z = b2j + p.x + p.y;
                zbuf[r * G4_ + j] = isg ? tanh_(z) : sigm_(z);
            }
        }
        __syncthreads();
        {
            float iv = zbuf[r_ * G4_ + u_];
            float fv = zbuf[r_ * G4_ + 64 + u_];
            float gv = zbuf[r_ * G4_ + 128 + u_];
            float ov = zbuf[r_ * G4_ + 192 + u_];
            c2 = fv * c2 + iv * gv;
            hc[r_ * 128 + 64 + u_] = ov * tanh_(c2);  // h2_t
        }
        __syncthreads();

#pragma unroll
        for (int r = 0; r < NB_; r++) cur[r] = nxt[r];
    }

    // final h2 -> global
    g_h2[(b0 + r_) * D_ + u_] = hc[r_ * 128 + 64 + u_];
}

// ---------------------------------------------------------------------------
// Kernel 3: heads.  out[0:1024] = softmax head, out[1024:2048] = langmodel.
// ---------------------------------------------------------------------------
__global__ void k_head(const float* __restrict__ aux,
                       const float* __restrict__ Wlm, const float* __restrict__ blm,
                       const float* __restrict__ gamma, const float* __restrict__ beta,
                       const float* __restrict__ mean, const float* __restrict__ var,
                       const float* __restrict__ W3, const float* __restrict__ b3,
                       const float* __restrict__ W4, const float* __restrict__ b4,
                       float* __restrict__ out) {
    int b = blockIdx.x;
    int t = threadIdx.x;  // 128 threads
    __shared__ float h2s[64], zbn[66], hid[32];

    if (t < 64) h2s[t] = g_h2[b * 64 + t];
    __syncthreads();
    if (t < 66) {
        float z = (t < 2) ? aux[b * 2 + t] : h2s[t - 2];
        zbn[t] = gamma[t] * (z - mean[t]) * rsqrtf(var[t] + 1e-3f) + beta[t];
    }
    __syncthreads();
    if (t < 32) {
        float acc = b3[t];
#pragma unroll
        for (int k = 0; k < 66; k++) acc += zbn[k] * __ldg(&W3[k * 32 + t]);
        hid[t] = fmaxf(acc, 0.0f);
    }
    __syncthreads();
    if (t == 0) {
        float o0 = b4[0], o1 = b4[1];
#pragma unroll
        for (int k = 0; k < 32; k++) {
            o0 += hid[k] * __ldg(&W4[k * 2 + 0]);
            o1 += hid[k] * __ldg(&W4[k * 2 + 1]);
        }
        float m = fmaxf(o0, o1);
        float e0 = __expf(o0 - m), e1 = __expf(o1 - m);
        float inv = 1.0f / (e0 + e1);
        out[b * 2 + 0] = e0 * inv;
        out[b * 2 + 1] = e1 * inv;

        float l0 = blm[0], l1 = blm[1];
#pragma unroll
        for (int k = 0; k < 64; k++) {
            l0 += h2s[k] * __ldg(&Wlm[k * 2 + 0]);
            l1 += h2s[k] * __ldg(&Wlm[k * 2 + 1]);
        }
        out[B_ * 2 + b * 2 + 0] = sigm_(l0);
        out[B_ * 2 + b * 2 + 1] = sigm_(l1);
    }
}

// ---------------------------------------------------------------------------
// launcher
// inputs: 0 aux_in, 1 code_in, 2 emb, 3 W1, 4 U1, 5 b1, 6 W2, 7 U2, 8 b2,
//         9 Wlm, 10 blm, 11 bn_gamma, 12 bn_beta, 13 bn_mean, 14 bn_var,
//         15 W3, 16 b3, 17 W4, 18 b4
// ---------------------------------------------------------------------------
extern "C" void kernel_launch(void* const* d_in, const int* in_sizes, int n_in,
                              void* d_out, int out_size) {
    const float* aux   = (const float*)d_in[0];
    const int*   code  = (const int*)d_in[1];
    const float* emb   = (const float*)d_in[2];
    const float* W1    = (const float*)d_in[3];
    const float* U1    = (const float*)d_in[4];
    const float* b1    = (const float*)d_in[5];
    const float* W2    = (const float*)d_in[6];
    const float* U2    = (const float*)d_in[7];
    const float* b2    = (const float*)d_in[8];
    const float* Wlm   = (const float*)d_in[9];
    const float* blm   = (const float*)d_in[10];
    const float* gamma = (const float*)d_in[11];
    const float* beta  = (const float*)d_in[12];
    const float* mean  = (const float*)d_in[13];
    const float* var   = (const float*)d_in[14];
    const float* W3    = (const float*)d_in[15];
    const float* b3    = (const float*)d_in[16];
    const float* W4    = (const float*)d_in[17];
    const float* b4    = (const float*)d_in[18];
    float* out = (float*)d_out;

    cudaFuncSetAttribute(k_lstm, cudaFuncAttributeMaxDynamicSharedMemorySize,
                         SMEM_BYTES);

    k_embproj<<<V_, 256>>>(emb, W1, b1);
    k_lstm<<<NBLK_, THR_, SMEM_BYTES>>>(code, U1, W2, U2, b2);
    k_head<<<B_, 128>>>(aux, Wlm, blm, gamma, beta, mean, var, W3, b3, W4, b4,
                        out);
}

// round 2
// speedup vs baseline: 1.3131x; 1.3131x over previous
#include <cuda_runtime.h>
#include <cuda_bf16.h>
#include <cstdint>

// ---------------------------------------------------------------------------
// RnnTfModel: emb lookup -> LSTM1 (seq) -> LSTM2 (last) -> heads
// B=512, T=1024, D=H=64, 4H=256, V=8193
//
// R2: weights register-resident (192 regs/thread of packed f32x2 pairs),
//     h broadcast from smem, 3 barriers/step (double-buffered gate scratch).
// ---------------------------------------------------------------------------

#define B_   512
#define T_   1024
#define D_   64
#define G4_  256
#define V_   8193
#define NB_  4
#define NBLK_ 128
#define THR_ 256

using ull = unsigned long long;

__device__ float g_table[V_ * G4_];   // projected embedding table (8.4 MB)
__device__ float g_h2[B_ * D_];       // final layer-2 hidden state

__device__ __forceinline__ void ffma2(ull& d, ull a, ull b) {
    asm("fma.rn.f32x2 %0, %1, %2, %0;" : "+l"(d) : "l"(a), "l"(b));
}
__device__ __forceinline__ float2 unpack2(ull v) {
    float2 f;
    asm("mov.b64 {%0, %1}, %2;" : "=f"(f.x), "=f"(f.y) : "l"(v));
    return f;
}
__device__ __forceinline__ ull pack2(float lo, float hi) {
    ull v;
    asm("mov.b64 %0, {%1, %2};" : "=l"(v) : "f"(lo), "f"(hi));
    return v;
}
__device__ __forceinline__ float sigm_(float x) {
    return 1.0f / (1.0f + __expf(-x));
}
__device__ __forceinline__ float tanh_(float x) {
    float e = __expf(-2.0f * x);
    return (1.0f - e) / (1.0f + e);
}

// ---------------------------------------------------------------------------
// Kernel 1: projected embedding table  (g_table = emb @ W1 + b1)
// ---------------------------------------------------------------------------
__global__ void k_embproj(const float* __restrict__ emb,
                          const float* __restrict__ W1,
                          const float* __restrict__ b1) {
    int v = blockIdx.x;
    int j = threadIdx.x;  // 256 threads, one output each
    __shared__ float e[D_];
    if (j < D_) e[j] = emb[v * D_ + j];
    __syncthreads();
    float acc = b1[j];
#pragma unroll
    for (int k = 0; k < D_; k++) acc += e[k] * __ldg(&W1[k * G4_ + j]);
    g_table[v * G4_ + j] = acc;
}

// ---------------------------------------------------------------------------
// Kernel 2: fused persistent 2-layer LSTM, weights in registers.
// Thread j in [0,256) owns output column j of both layers' gate matvecs.
// smem: hc   [4 rows x 128] : [0,64)=h1, [64,128)=h2  (16B-aligned)
//       zbuf1/zbuf2 [4 rows x 256] gate activations (double buffer)
//       code_s [4 rows x 1024]
// ---------------------------------------------------------------------------
__global__ void __launch_bounds__(THR_, 1)
k_lstm(const int* __restrict__ code_in,
       const float* __restrict__ U1,
       const float* __restrict__ W2,
       const float* __restrict__ U2,
       const float* __restrict__ b2) {
    __shared__ __align__(16) float hc[NB_ * 128];
    __shared__ float zbuf1[NB_ * G4_];
    __shared__ float zbuf2[NB_ * G4_];
    __shared__ int code_s[NB_ * T_];

    const int j  = threadIdx.x;
    const int r_ = j >> 6;      // row for c/h update role
    const int u_ = j & 63;      // hidden unit for c/h update role
    const int b0 = blockIdx.x * NB_;

    // ---- weights into registers (packed over adjacent k) ----
    ull w1r[32];                 // U1[2k2][j], U1[2k2+1][j]
#pragma unroll
    for (int k2 = 0; k2 < 32; k2++)
        w1r[k2] = pack2(__ldg(&U1[(2 * k2) * G4_ + j]),
                        __ldg(&U1[(2 * k2 + 1) * G4_ + j]));
    ull w2r[64];                 // [W2;U2] stacked over k=0..127
#pragma unroll
    for (int k2 = 0; k2 < 32; k2++) {
        w2r[k2]      = pack2(__ldg(&W2[(2 * k2) * G4_ + j]),
                             __ldg(&W2[(2 * k2 + 1) * G4_ + j]));
        w2r[32 + k2] = pack2(__ldg(&U2[(2 * k2) * G4_ + j]),
                             __ldg(&U2[(2 * k2 + 1) * G4_ + j]));
    }

    // ---- load codes for this block's 4 rows ----
    for (int i = j; i < NB_ * T_; i += THR_) {
        int r = i >> 10, t = i & (T_ - 1);
        code_s[i] = code_in[(b0 + r) * T_ + t];
    }
    // ---- zero h state ----
    hc[j] = 0.0f;
    hc[j + 256] = 0.0f;
    __syncthreads();

    const float b2j = b2[j];
    float c1 = 0.0f, c2 = 0.0f;

    // prefetch xz for t=0
    float cur[NB_];
#pragma unroll
    for (int r = 0; r < NB_; r++)
        cur[r] = __ldg(&g_table[(size_t)code_s[r * T_] * G4_ + j]);

    const bool isg = ((j >> 6) == 2);  // gate index 2 = g (tanh)

    for (int t = 0; t < T_; t++) {
        // prefetch next timestep's input projection
        float nxt[NB_];
        int tn = (t + 1 < T_) ? (t + 1) : (T_ - 1);
#pragma unroll
        for (int r = 0; r < NB_; r++)
            nxt[r] = __ldg(&g_table[(size_t)code_s[r * T_ + tn] * G4_ + j]);

        // ---------------- layer 1 matvec: z1 = xz + h1 @ U1 ----------------
        ull a0 = 0, a1 = 0, a2 = 0, a3 = 0;
#pragma unroll
        for (int k4 = 0; k4 < 16; k4++) {
            ulonglong2 h0 = *(const ulonglong2*)&hc[0 * 128 + 4 * k4];
            ulonglong2 h1 = *(const ulonglong2*)&hc[1 * 128 + 4 * k4];
            ulonglong2 h2 = *(const ulonglong2*)&hc[2 * 128 + 4 * k4];
            ulonglong2 h3 = *(const ulonglong2*)&hc[3 * 128 + 4 * k4];
            ffma2(a0, h0.x, w1r[2 * k4]);     ffma2(a1, h1.x, w1r[2 * k4]);
            ffma2(a2, h2.x, w1r[2 * k4]);     ffma2(a3, h3.x, w1r[2 * k4]);
            ffma2(a0, h0.y, w1r[2 * k4 + 1]); ffma2(a1, h1.y, w1r[2 * k4 + 1]);
            ffma2(a2, h2.y, w1r[2 * k4 + 1]); ffma2(a3, h3.y, w1r[2 * k4 + 1]);
        }
        {
            ull aa[NB_] = {a0, a1, a2, a3};
#pragma unroll
            for (int r = 0; r < NB_; r++) {
                float2 p = unpack2(aa[r]);
                float z = cur[r] + p.x + p.y;
                zbuf1[r * G4_ + j] = isg ? tanh_(z) : sigm_(z);
            }
        }
        __syncthreads();   // sync1: zbuf1 ready
        {
            float iv = zbuf1[r_ * G4_ + u_];
            float fv = zbuf1[r_ * G4_ + 64 + u_];
            float gv = zbuf1[r_ * G4_ + 128 + u_];
            float ov = zbuf1[r_ * G4_ + 192 + u_];
            c1 = fv * c1 + iv * gv;
            hc[r_ * 128 + u_] = ov * tanh_(c1);   // h1_t
        }
        __syncthreads();   // sync2: h1_t ready

        // -------- layer 2 matvec: z2 = b2 + [h1_t, h2_{t-1}] @ [W2;U2] -----
        a0 = a1 = a2 = a3 = 0;
#pragma unroll
        for (int k4 = 0; k4 < 32; k4++) {
            ulonglong2 h0 = *(const ulonglong2*)&hc[0 * 128 + 4 * k4];
            ulonglong2 h1 = *(const ulonglong2*)&hc[1 * 128 + 4 * k4];
            ulonglong2 h2 = *(const ulonglong2*)&hc[2 * 128 + 4 * k4];
            ulonglong2 h3 = *(const ulonglong2*)&hc[3 * 128 + 4 * k4];
            ffma2(a0, h0.x, w2r[2 * k4]);     ffma2(a1, h1.x, w2r[2 * k4]);
            ffma2(a2, h2.x, w2r[2 * k4]);     ffma2(a3, h3.x, w2r[2 * k4]);
            ffma2(a0, h0.y, w2r[2 * k4 + 1]); ffma2(a1, h1.y, w2r[2 * k4 + 1]);
            ffma2(a2, h2.y, w2r[2 * k4 + 1]); ffma2(a3, h3.y, w2r[2 * k4 + 1]);
        }
        {
            ull aa[NB_] = {a0, a1, a2, a3};
#pragma unroll
            for (int r = 0; r < NB_; r++) {
                float2 p = unpack2(aa[r]);
                float z = b2j + p.x + p.y;
                zbuf2[r * G4_ + j] = isg ? tanh_(z) : sigm_(z);
            }
        }
        __syncthreads();   // sync3: zbuf2 ready
        {
            float iv = zbuf2[r_ * G4_ + u_];
            float fv = zbuf2[r_ * G4_ + 64 + u_];
            float gv = zbuf2[r_ * G4_ + 128 + u_];
            float ov = zbuf2[r_ * G4_ + 192 + u_];
            c2 = fv * c2 + iv * gv;
            hc[r_ * 128 + 64 + u_] = ov * tanh_(c2);  // h2_t
        }
        // NOTE: no barrier here. h2_t is only read in next step's layer-2
        // matvec, which is separated from this write by sync1 and sync2 of
        // step t+1. WAR on zbuf2 is protected by sync1 of t+1; WAR on hc[h2]
        // against this step's layer-2 reads is impossible (reads precede
        // sync3, write follows it).

#pragma unroll
        for (int r = 0; r < NB_; r++) cur[r] = nxt[r];
    }

    __syncthreads();
    // final h2 -> global
    g_h2[(b0 + r_) * D_ + u_] = hc[r_ * 128 + 64 + u_];
}

// ---------------------------------------------------------------------------
// Kernel 3: heads.  out[0:1024] = softmax head, out[1024:2048] = langmodel.
// ---------------------------------------------------------------------------
__global__ void k_head(const float* __restrict__ aux,
                       const float* __restrict__ Wlm, const float* __restrict__ blm,
                       const float* __restrict__ gamma, const float* __restrict__ beta,
                       const float* __restrict__ mean, const float* __restrict__ var,
                       const float* __restrict__ W3, const float* __restrict__ b3,
                       const float* __restrict__ W4, const float* __restrict__ b4,
                       float* __restrict__ out) {
    int b = blockIdx.x;
    int t = threadIdx.x;  // 128 threads
    __shared__ float h2s[64], zbn[66], hid[32];

    if (t < 64) h2s[t] = g_h2[b * 64 + t];
    __syncthreads();
    if (t < 66) {
        float z = (t < 2) ? aux[b * 2 + t] : h2s[t - 2];
        zbn[t] = gamma[t] * (z - mean[t]) * rsqrtf(var[t] + 1e-3f) + beta[t];
    }
    __syncthreads();
    if (t < 32) {
        float acc = b3[t];
#pragma unroll
        for (int k = 0; k < 66; k++) acc += zbn[k] * __ldg(&W3[k * 32 + t]);
        hid[t] = fmaxf(acc, 0.0f);
    }
    __syncthreads();
    if (t == 0) {
        float o0 = b4[0], o1 = b4[1];
#pragma unroll
        for (int k = 0; k < 32; k++) {
            o0 += hid[k] * __ldg(&W4[k * 2 + 0]);
            o1 += hid[k] * __ldg(&W4[k * 2 + 1]);
        }
        float m = fmaxf(o0, o1);
        float e0 = __expf(o0 - m), e1 = __expf(o1 - m);
        float inv = 1.0f / (e0 + e1);
        out[b * 2 + 0] = e0 * inv;
        out[b * 2 + 1] = e1 * inv;

        float l0 = blm[0], l1 = blm[1];
#pragma unroll
        for (int k = 0; k < 64; k++) {
            l0 += h2s[k] * __ldg(&Wlm[k * 2 + 0]);
            l1 += h2s[k] * __ldg(&Wlm[k * 2 + 1]);
        }
        out[B_ * 2 + b * 2 + 0] = sigm_(l0);
        out[B_ * 2 + b * 2 + 1] = sigm_(l1);
    }
}

// ---------------------------------------------------------------------------
// launcher
// inputs: 0 aux_in, 1 code_in, 2 emb, 3 W1, 4 U1, 5 b1, 6 W2, 7 U2, 8 b2,
//         9 Wlm, 10 blm, 11 bn_gamma, 12 bn_beta, 13 bn_mean, 14 bn_var,
//         15 W3, 16 b3, 17 W4, 18 b4
// ---------------------------------------------------------------------------
extern "C" void kernel_launch(void* const* d_in, const int* in_sizes, int n_in,
                              void* d_out, int out_size) {
    const float* aux   = (const float*)d_in[0];
    const int*   code  = (const int*)d_in[1];
    const float* emb   = (const float*)d_in[2];
    const float* W1    = (const float*)d_in[3];
    const float* U1    = (const float*)d_in[4];
    const float* b1    = (const float*)d_in[5];
    const float* W2    = (const float*)d_in[6];
    const float* U2    = (const float*)d_in[7];
    const float* b2    = (const float*)d_in[8];
    const float* Wlm   = (const float*)d_in[9];
    const float* blm   = (const float*)d_in[10];
    const float* gamma = (const float*)d_in[11];
    const float* beta  = (const float*)d_in[12];
    const float* mean  = (const float*)d_in[13];
    const float* var   = (const float*)d_in[14];
    const float* W3    = (const float*)d_in[15];
    const float* b3    = (const float*)d_in[16];
    const float* W4    = (const float*)d_in[17];
    const float* b4    = (const float*)d_in[18];
    float* out = (float*)d_out;

    k_embproj<<<V_, 256>>>(emb, W1, b1);
    k_lstm<<<NBLK_, THR_>>>(code, U1, W2, U2, b2);
    k_head<<<B_, 128>>>(aux, Wlm, blm, gamma, beta, mean, var, W3, b3, W4, b4,
                        out);
}